// round 6
// baseline (speedup 1.0000x reference)
#include <cuda_runtime.h>
#include <cstdint>
#include <cub/cub.cuh>

// Problem constants
#define C_DIM     4096
#define NUMEL_D   16777216.0
#define MAX_K     4500000               // >= S + R = 4,404,019
#define M_SORT    1310720               // R + 256K slack (candidate sort size, fixed for graph)
#define HIST_BINS (1u << 18)            // ordkey >> 13
#define NBUCK     4096
#define CAP       2048                  // max elements per bucket (Poisson mean ~1075)
#define TEMP_BYTES (96u * 1024u * 1024u)

// Static device scratch (allocation-free per harness rules)
__device__ unsigned long long g_z[MAX_K]; // scatter: (bin12<<32)|origidx
__device__ uint32_t g_sv[MAX_K];          // scatter: value bits
__device__ uint32_t g_w [MAX_K];          // per-slot head ordkey (0xFFFFFFFF = empty)
__device__ uint32_t g_kk[MAX_K];          // per-slot head key24
__device__ uint32_t g_fl[MAX_K];          // flags
__device__ uint32_t g_sc[MAX_K];          // scan out
__device__ uint32_t g_goff[NBUCK];        // bucket histogram
__device__ uint32_t g_boff[NBUCK + 1];    // bucket offsets
__device__ uint32_t g_cur[NBUCK];         // scatter cursors
__device__ uint32_t g_hist[HIST_BINS];
__device__ uint32_t g_super[1024];
__device__ uint32_t g_B[1];
__device__ unsigned char g_temp[TEMP_BYTES];
// arena: [0) cand_ord, [1) cand_key, [2) sort_ord, [3) sort_key (M_SORT u32 each), then cub temp

static __device__ __forceinline__ uint32_t f32_to_ord(uint32_t b) {
    return b ^ ((uint32_t)((int32_t)b >> 31) | 0x80000000u);
}

static __device__ __forceinline__ uint32_t make_key(const int* samp, const int* ridx,
                                                    int S, int i) {
    if (i < S) return (uint32_t)samp[i];
    int r = i - S;
    return (uint32_t)ridx[2 * r] * (uint32_t)C_DIM + (uint32_t)ridx[2 * r + 1];
}

__global__ void hist_kernel(const int* __restrict__ samp, const int* __restrict__ ridx,
                            int S, int K, uint32_t* __restrict__ goff) {
    int i = blockIdx.x * blockDim.x + threadIdx.x;
    if (i >= K) return;
    uint32_t key = make_key(samp, ridx, S, i);
    atomicAdd(&goff[key >> 12], 1u);
}

__global__ void offsets_kernel(const uint32_t* __restrict__ goff,
                               uint32_t* __restrict__ boff,
                               uint32_t* __restrict__ cur, int K) {
    typedef cub::BlockScan<uint32_t, 1024> BS;
    __shared__ typename BS::TempStorage ts;
    int tid = threadIdx.x;
    uint32_t items[4], sum = 0;
    #pragma unroll
    for (int i = 0; i < 4; i++) { items[i] = goff[tid * 4 + i]; sum += items[i]; }
    uint32_t tbase;
    BS(ts).ExclusiveSum(sum, tbase);
    uint32_t run = tbase;
    #pragma unroll
    for (int i = 0; i < 4; i++) {
        boff[tid * 4 + i] = run;
        cur[tid * 4 + i]  = run;
        run += items[i];
    }
    if (tid == 1023) boff[NBUCK] = (uint32_t)K;
}

__global__ void scatter_kernel(const int* __restrict__ samp, const int* __restrict__ ridx,
                               const float* __restrict__ grad, const float* __restrict__ rval,
                               int S, int K, float adj,
                               uint32_t* __restrict__ cur,
                               unsigned long long* __restrict__ zipA,
                               uint32_t* __restrict__ sval) {
    int i = blockIdx.x * blockDim.x + threadIdx.x;
    if (i >= K) return;
    uint32_t key = make_key(samp, ridx, S, i);
    float v = (i < S) ? fabsf(grad[i]) : adj * rval[i - S];
    uint32_t p = atomicAdd(&cur[key >> 12], 1u);
    zipA[p] = ((unsigned long long)(key & 0xFFFu) << 32) | (unsigned long long)(uint32_t)i;
    sval[p] = __float_as_uint(v);
}

// One block per bucket: group by low-12 key, restore original order within each
// key group (sort by origidx), sum sequentially, emit head (ordkey,key) densely
// in ascending-bin order at w[start + headrank].
__global__ void __launch_bounds__(256) bucket_kernel(
        const unsigned long long* __restrict__ zipA,
        const uint32_t* __restrict__ sval,
        const uint32_t* __restrict__ boff,
        uint32_t* __restrict__ w, uint32_t* __restrict__ kk,
        uint32_t* __restrict__ hist) {
    __shared__ uint32_t s_cnt[NBUCK];          // running counters (base after scan, end after scatter)
    __shared__ uint16_t s_base[NBUCK];         // bin start (<= CAP fits u16)
    __shared__ uint32_t s_meta[CAP];           // origidx
    __shared__ uint32_t s_val[CAP];            // value bits
    typedef cub::BlockScan<uint32_t, 256> BS;
    __shared__ typename BS::TempStorage s_scan;

    int b = blockIdx.x, tid = threadIdx.x;
    uint32_t start = boff[b], end = boff[b + 1];
    uint32_t n = end - start;
    if (n > CAP) n = CAP;                      // statistically impossible; memory safety

    for (int i = tid; i < NBUCK; i += 256) s_cnt[i] = 0;
    __syncthreads();

    uint32_t l_bin[8], l_idx[8], l_val[8];
    int nl = 0;
    for (uint32_t i = tid; i < n; i += 256) {
        unsigned long long z = zipA[start + i];
        l_bin[nl] = (uint32_t)(z >> 32);
        l_idx[nl] = (uint32_t)z;
        l_val[nl] = sval[start + i];
        atomicAdd(&s_cnt[l_bin[nl]], 1u);
        nl++;
    }
    __syncthreads();

    // exclusive scan of bin counts (16 bins/thread)
    uint32_t items[16], sum = 0;
    #pragma unroll
    for (int i = 0; i < 16; i++) { items[i] = s_cnt[tid * 16 + i]; sum += items[i]; }
    uint32_t tbase;
    BS(s_scan).ExclusiveSum(sum, tbase);
    __syncthreads();
    uint32_t run = tbase;
    #pragma unroll
    for (int i = 0; i < 16; i++) { s_base[tid * 16 + i] = (uint16_t)run; run += items[i]; }
    __syncthreads();
    for (int i = tid; i < NBUCK; i += 256) s_cnt[i] = s_base[i];
    __syncthreads();

    // scatter into bin-ordered smem
    for (int c = 0; c < nl; c++) {
        uint32_t p = atomicAdd(&s_cnt[l_bin[c]], 1u);
        s_meta[p] = l_idx[c];
        s_val[p]  = l_val[c];
    }
    __syncthreads();

    // occupancy scan -> headrank per nonempty bin (ascending-bin order)
    uint32_t occ[16], osum = 0;
    #pragma unroll
    for (int i = 0; i < 16; i++) {
        uint32_t c = s_cnt[tid * 16 + i] - (uint32_t)s_base[tid * 16 + i];
        occ[i] = (c > 0) ? 1u : 0u;
        osum += occ[i];
    }
    uint32_t obase;
    BS(s_scan).ExclusiveSum(osum, obase);

    uint32_t orun = obase;
    #pragma unroll
    for (int i = 0; i < 16; i++) {
        uint32_t bin = tid * 16 + i;
        uint32_t lo = (uint32_t)s_base[bin];
        uint32_t hi = s_cnt[bin];
        uint32_t hp = orun;
        orun += occ[i];
        uint32_t c = hi - lo;
        if (c == 0) continue;
        // restore original order within the key group (bins disjoint per thread)
        for (uint32_t a = lo + 1; a < hi; a++) {
            uint32_t m = s_meta[a], v = s_val[a];
            uint32_t t = a;
            while (t > lo && s_meta[t - 1] > m) {
                s_meta[t] = s_meta[t - 1];
                s_val[t]  = s_val[t - 1];
                t--;
            }
            s_meta[t] = m; s_val[t] = v;
        }
        float s = 0.0f;
        for (uint32_t a = lo; a < hi; a++) s += __uint_as_float(s_val[a]);  // orig order => bit-exact
        uint32_t ordk = ~f32_to_ord(__float_as_uint(s));
        w[start + hp]  = ordk;
        kk[start + hp] = ((uint32_t)b << 12) | bin;
        atomicAdd(&hist[ordk >> 13], 1u);
    }
}

__global__ void coarse_kernel(const uint32_t* __restrict__ hist,
                              uint32_t* __restrict__ super) {
    typedef cub::BlockReduce<uint32_t, 256> BR;
    __shared__ typename BR::TempStorage ts;
    uint32_t v = hist[blockIdx.x * 256 + threadIdx.x];
    uint32_t s = BR(ts).Sum(v);
    if (threadIdx.x == 0) super[blockIdx.x] = s;
}

__global__ void select_kernel(const uint32_t* __restrict__ super,
                              const uint32_t* __restrict__ hist,
                              uint32_t R, uint32_t* __restrict__ Bout) {
    typedef cub::BlockScan<uint32_t, 1024> BS;
    __shared__ typename BS::TempStorage ts;
    __shared__ uint32_t s_sb, s_base2;
    if (threadIdx.x == 0) { s_sb = 0xFFFFFFFFu; s_base2 = 0; }
    __syncthreads();
    uint32_t v = super[threadIdx.x];
    uint32_t inc;
    BS(ts).InclusiveSum(v, inc);
    if (inc >= R && (inc - v) < R) { s_sb = threadIdx.x; s_base2 = inc - v; }
    __syncthreads();
    if (s_sb == 0xFFFFFFFFu) {
        if (threadIdx.x == 0) Bout[0] = 0xFFFFFFFFu;
        return;
    }
    uint32_t sb = s_sb, base = s_base2;
    __syncthreads();
    uint32_t h = (threadIdx.x < 256) ? hist[sb * 256 + threadIdx.x] : 0u;
    uint32_t inc1;
    BS(ts).InclusiveSum(h, inc1);
    if (threadIdx.x < 256) {
        uint32_t excl = inc1 - h;
        if (base + inc1 >= R && base + excl < R)
            Bout[0] = ((sb * 256u + threadIdx.x) + 1u) << 13;
    }
}

__global__ void flags_kernel(const uint32_t* __restrict__ w,
                             const uint32_t* __restrict__ Bp,
                             int K, uint32_t* __restrict__ flags) {
    int j = blockIdx.x * blockDim.x + threadIdx.x;
    if (j >= K) return;
    flags[j] = (w[j] < *Bp) ? 1u : 0u;
}

__global__ void compact_kernel(const uint32_t* __restrict__ w,
                               const uint32_t* __restrict__ kk,
                               const uint32_t* __restrict__ scan,
                               const uint32_t* __restrict__ Bp, int K,
                               uint32_t* __restrict__ cand_ord,
                               uint32_t* __restrict__ cand_key) {
    int j = blockIdx.x * blockDim.x + threadIdx.x;
    if (j >= K) return;
    uint32_t x = w[j];
    if (x < *Bp) {
        uint32_t p = scan[j];
        if (p < (uint32_t)M_SORT) {
            cand_ord[p] = x;
            cand_key[p] = kk[j];
        }
    }
}

__global__ void output_kernel(const uint32_t* __restrict__ sord,
                              const uint32_t* __restrict__ skey,
                              int R, int write_idx, int write_val, int val_off,
                              float* __restrict__ out) {
    int r = blockIdx.x * blockDim.x + threadIdx.x;
    if (r >= R) return;
    uint32_t key = skey[r];
    if (write_idx) {
        out[2 * r]     = (float)(key >> 12);
        out[2 * r + 1] = (float)(key & 4095u);
    }
    if (write_val) {
        uint32_t u = ~sord[r];
        uint32_t b = (u & 0x80000000u) ? (u ^ 0x80000000u) : ~u;
        out[val_off + r] = __uint_as_float(b);
    }
}

extern "C" void kernel_launch(void* const* d_in, const int* in_sizes, int n_in,
                              void* d_out, int out_size) {
    (void)n_in;
    const int*   samp = (const int*)d_in[0];
    const int*   ridx = (const int*)d_in[1];
    const float* rval = (const float*)d_in[2];
    const float* grad = (const float*)d_in[3];

    int S = in_sizes[0];
    int R = in_sizes[2];
    int K = S + R;
    if (K > MAX_K) K = MAX_K;

    double frac = (double)S / NUMEL_D;
    float adj = (float)(1.0 - frac * (1.0 - 0.95));

    unsigned long long* zipA;
    uint32_t *sv, *w, *kk, *fl, *sc, *goff, *boff, *cur, *hist, *super, *Bp;
    unsigned char* arena;
    cudaGetSymbolAddress((void**)&zipA, g_z);
    cudaGetSymbolAddress((void**)&sv, g_sv);
    cudaGetSymbolAddress((void**)&w,  g_w);
    cudaGetSymbolAddress((void**)&kk, g_kk);
    cudaGetSymbolAddress((void**)&fl, g_fl);
    cudaGetSymbolAddress((void**)&sc, g_sc);
    cudaGetSymbolAddress((void**)&goff, g_goff);
    cudaGetSymbolAddress((void**)&boff, g_boff);
    cudaGetSymbolAddress((void**)&cur, g_cur);
    cudaGetSymbolAddress((void**)&hist, g_hist);
    cudaGetSymbolAddress((void**)&super, g_super);
    cudaGetSymbolAddress((void**)&Bp, g_B);
    cudaGetSymbolAddress((void**)&arena, g_temp);

    uint32_t* cand_ord = (uint32_t*)arena;
    uint32_t* cand_key = cand_ord + M_SORT;
    uint32_t* sort_ord = cand_key + M_SORT;
    uint32_t* sort_key = sort_ord + M_SORT;
    void* tmp = (void*)(arena + (size_t)4 * M_SORT * sizeof(uint32_t) + 1024);
    const size_t TMPB = (size_t)64u << 20;

    const int BLK = 256;
    const int GK = (K + BLK - 1) / BLK;

    // per-replay re-init
    cudaMemsetAsync(goff, 0, NBUCK * sizeof(uint32_t));
    cudaMemsetAsync(hist, 0, HIST_BINS * sizeof(uint32_t));
    cudaMemsetAsync(w, 0xFF, (size_t)K * sizeof(uint32_t));

    // 1) bucket histogram + offsets
    hist_kernel<<<GK, BLK>>>(samp, ridx, S, K, goff);
    offsets_kernel<<<1, 1024>>>(goff, boff, cur, K);

    // 2) scatter into bucket-contiguous regions
    scatter_kernel<<<GK, BLK>>>(samp, ridx, grad, rval, S, K, adj, cur, zipA, sv);

    // 3) per-bucket group/sum/emit heads + value histogram
    bucket_kernel<<<NBUCK, 256>>>(zipA, sv, boff, w, kk, hist);

    // 4) threshold B (bin-granular, keeps all ties of the R-th element)
    coarse_kernel<<<1024, 256>>>(hist, super);
    select_kernel<<<1, 1024>>>(super, hist, (uint32_t)R, Bp);

    // 5) order-preserving compaction (ascending-key order retained)
    flags_kernel<<<GK, BLK>>>(w, Bp, K, fl);
    {
        size_t need = 0;
        cub::DeviceScan::ExclusiveSum(nullptr, need, fl, sc, K);
        if (need <= TMPB)
            cub::DeviceScan::ExclusiveSum(tmp, need, fl, sc, K);
    }
    cudaMemsetAsync(cand_ord, 0xFF, (size_t)M_SORT * sizeof(uint32_t));
    cudaMemsetAsync(cand_key, 0xFF, (size_t)M_SORT * sizeof(uint32_t));
    compact_kernel<<<GK, BLK>>>(w, kk, sc, Bp, K, cand_ord, cand_key);

    // 6) stable 32-bit pair sort: ascending ordkey == (value desc, key asc)
    {
        size_t need = 0;
        cub::DeviceRadixSort::SortPairs(nullptr, need, cand_ord, sort_ord,
                                        cand_key, sort_key, M_SORT, 0, 32);
        if (need <= TMPB)
            cub::DeviceRadixSort::SortPairs(tmp, need, cand_ord, sort_ord,
                                            cand_key, sort_key, M_SORT, 0, 32);
    }

    // 7) emit [new_index (R,2), top_vals (R)] as f32
    int write_idx = 1, write_val = 1, val_off = 2 * R;
    if (out_size == R)          { write_idx = 0; val_off = 0; }
    else if (out_size == 2 * R) { write_val = 0; }
    output_kernel<<<(R + BLK - 1) / BLK, BLK>>>(sort_ord, sort_key, R,
                                                write_idx, write_val, val_off,
                                                (float*)d_out);
}

// round 7
// speedup vs baseline: 1.0764x; 1.0764x over previous
#include <cuda_runtime.h>
#include <cstdint>
#include <cub/cub.cuh>

// Problem constants
#define C_DIM     4096
#define NUMEL     16777216
#define NUMEL_D   16777216.0
#define MAX_K     4500000               // >= S + R = 4,404,019
#define DUPN      524288                // cap for entries in groups >= 3 (expect ~150K)
#define M2        1114112               // candidate sort size: R + 64K slack
#define HIST_BINS (1u << 18)            // ordkey >> 13
#define SENT      0xFFFFFFFFu

// Static device scratch (allocation-free per harness rules)
__device__ uint32_t g_cnt[NUMEL / 4];        // packed u8 counts, 16MB
__device__ uint32_t g_vslot[NUMEL];          // pair-exchange slots, 64MB
__device__ unsigned long long g_heads[MAX_K];// per-entry head zip (~0 = none)
__device__ uint32_t g_dk[DUPN], g_dk2[DUPN]; // dup keys (in/out)
__device__ uint32_t g_dp[DUPN], g_dp2[DUPN]; // dup slot payload (in/out)
__device__ uint32_t g_di[DUPN], g_dv[DUPN];  // dup origidx / value bits by slot
__device__ uint32_t g_cord[M2], g_ckey[M2];  // candidates
__device__ uint32_t g_sord[M2], g_skey[M2];  // sorted candidates
__device__ uint32_t g_hist[HIST_BINS];
__device__ uint32_t g_super[1024];
__device__ uint32_t g_B[1];
__device__ uint32_t g_dcur[1], g_ccur[1];
__device__ unsigned char g_temp[32u << 20];  // cub temp

static __device__ __forceinline__ uint32_t f32_to_ord(uint32_t b) {
    return b ^ ((uint32_t)((int32_t)b >> 31) | 0x80000000u);
}
static __device__ __forceinline__ unsigned long long make_zip(float sum, uint32_t key) {
    uint32_t ordk = ~f32_to_ord(__float_as_uint(sum));   // <= 0x7FFFFFFF (sum >= 0)
    return ((unsigned long long)ordk << 24) | (unsigned long long)key;
}
static __device__ __forceinline__ uint32_t make_key(const int* samp, const int* ridx,
                                                    int S, int i) {
    if (i < S) return (uint32_t)samp[i];
    int r = i - S;
    return (uint32_t)ridx[2 * r] * (uint32_t)C_DIM + (uint32_t)ridx[2 * r + 1];
}

__global__ void count_kernel(const int* __restrict__ samp, const int* __restrict__ ridx,
                             int S, int K, uint32_t* __restrict__ cnt) {
    int i = blockIdx.x * blockDim.x + threadIdx.x;
    if (i >= K) return;
    uint32_t key = make_key(samp, ridx, S, i);
    atomicAdd(&cnt[key >> 2], 1u << ((key & 3u) * 8u));
}

__global__ void classify_kernel(const int* __restrict__ samp, const int* __restrict__ ridx,
                                const float* __restrict__ grad, const float* __restrict__ rval,
                                int S, int K, float adj,
                                const uint32_t* __restrict__ cnt,
                                uint32_t* __restrict__ vslot,
                                unsigned long long* __restrict__ heads,
                                uint32_t* __restrict__ dcur,
                                uint32_t* __restrict__ dk, uint32_t* __restrict__ dp,
                                uint32_t* __restrict__ di, uint32_t* __restrict__ dv,
                                uint32_t* __restrict__ hist) {
    int i = blockIdx.x * blockDim.x + threadIdx.x;
    if (i >= K) return;
    uint32_t key = make_key(samp, ridx, S, i);
    float v = (i < S) ? fabsf(grad[i]) : adj * rval[i - S];
    uint32_t bits = __float_as_uint(v);
    uint32_t c = (cnt[key >> 2] >> ((key & 3u) * 8u)) & 0xFFu;
    if (c == 1u) {
        unsigned long long z = make_zip(v, key);      // singleton: sum == value (0+v == v)
        heads[i] = z;
        atomicAdd(&hist[(uint32_t)(z >> 24) >> 13], 1u);
    } else if (c == 2u) {
        uint32_t old = atomicExch(&vslot[key], bits); // serialized: exactly one sees partner
        if (old == SENT) {
            heads[i] = ~0ull;
        } else {
            float s = __uint_as_float(bits) + __uint_as_float(old);  // commutative => exact
            unsigned long long z = make_zip(s, key);
            heads[i] = z;
            atomicAdd(&hist[(uint32_t)(z >> 24) >> 13], 1u);
        }
    } else {
        heads[i] = ~0ull;
        uint32_t p = atomicAdd(dcur, 1u);
        if (p < (uint32_t)DUPN) {
            dk[p] = key; dp[p] = p; di[p] = (uint32_t)i; dv[p] = bits;
        }
    }
}

// Groups >= 3: dup list sorted by key; restore original order via repeated
// min-origidx selection (groups tiny), sum sequentially => bit-exact.
__global__ void dupsum_kernel(const uint32_t* __restrict__ dk2,
                              const uint32_t* __restrict__ dp2,
                              const uint32_t* __restrict__ di,
                              const uint32_t* __restrict__ dv,
                              unsigned long long* __restrict__ heads,
                              uint32_t* __restrict__ hist) {
    int j = blockIdx.x * blockDim.x + threadIdx.x;
    if (j >= DUPN) return;
    uint32_t k = dk2[j];
    if (k & 0xFF000000u) return;                       // pad
    if (j > 0 && dk2[j - 1] == k) return;              // not group head
    int e = j + 1;
    while (e < DUPN && dk2[e] == k) e++;
    int L = e - j;
    uint32_t lastEx = 0, firstidx = 0;
    float sum = 0.0f;
    for (int s = 0; s < L; s++) {
        uint32_t best = 0xFFFFFFFFu, bv = 0;
        for (int q = j; q < e; q++) {
            uint32_t slot = dp2[q];
            uint32_t oi = di[slot];
            if (oi >= lastEx && oi < best) { best = oi; bv = dv[slot]; }
        }
        if (s == 0) firstidx = best;
        sum += __uint_as_float(bv);                    // original order => exact
        lastEx = best + 1u;
    }
    unsigned long long z = make_zip(sum, k);
    heads[firstidx] = z;
    atomicAdd(&hist[(uint32_t)(z >> 24) >> 13], 1u);
}

__global__ void coarse_kernel(const uint32_t* __restrict__ hist,
                              uint32_t* __restrict__ super) {
    typedef cub::BlockReduce<uint32_t, 256> BR;
    __shared__ typename BR::TempStorage ts;
    uint32_t v = hist[blockIdx.x * 256 + threadIdx.x];
    uint32_t s = BR(ts).Sum(v);
    if (threadIdx.x == 0) super[blockIdx.x] = s;
}

__global__ void select_kernel(const uint32_t* __restrict__ super,
                              const uint32_t* __restrict__ hist,
                              uint32_t R, uint32_t* __restrict__ Bout) {
    typedef cub::BlockScan<uint32_t, 1024> BS;
    __shared__ typename BS::TempStorage ts;
    __shared__ uint32_t s_sb, s_base2;
    if (threadIdx.x == 0) { s_sb = 0xFFFFFFFFu; s_base2 = 0; }
    __syncthreads();
    uint32_t v = super[threadIdx.x];
    uint32_t inc;
    BS(ts).InclusiveSum(v, inc);
    if (inc >= R && (inc - v) < R) { s_sb = threadIdx.x; s_base2 = inc - v; }
    __syncthreads();
    if (s_sb == 0xFFFFFFFFu) {
        if (threadIdx.x == 0) Bout[0] = 0xFFFFFFFFu;
        return;
    }
    uint32_t sb = s_sb, base = s_base2;
    __syncthreads();
    uint32_t h = (threadIdx.x < 256) ? hist[sb * 256 + threadIdx.x] : 0u;
    uint32_t inc1;
    BS(ts).InclusiveSum(h, inc1);
    if (threadIdx.x < 256) {
        uint32_t excl = inc1 - h;
        if (base + inc1 >= R && base + excl < R)
            Bout[0] = ((sb * 256u + threadIdx.x) + 1u) << 13;
    }
}

__global__ void filter_kernel(const unsigned long long* __restrict__ heads,
                              const uint32_t* __restrict__ Bp, int K,
                              uint32_t* __restrict__ ccur,
                              uint32_t* __restrict__ cord,
                              uint32_t* __restrict__ ckey) {
    int i = blockIdx.x * blockDim.x + threadIdx.x;
    if (i >= K) return;
    unsigned long long z = heads[i];
    if (z < ((unsigned long long)(*Bp) << 24)) {
        uint32_t p = atomicAdd(ccur, 1u);
        if (p < (uint32_t)M2) {
            cord[p] = (uint32_t)(z >> 24);
            ckey[p] = (uint32_t)z & 0xFFFFFFu;
        }
    }
}

// After stable sort by ordkey, re-sort keys ascending within each equal-ordkey
// run => exact lax.top_k tie-break, independent of filter arrival order.
__global__ void tiefix_kernel(const uint32_t* __restrict__ sord,
                              uint32_t* __restrict__ skey) {
    int j = blockIdx.x * blockDim.x + threadIdx.x;
    if (j >= M2) return;
    uint32_t o = sord[j];
    if (o == 0xFFFFFFFFu) return;                    // pad (real ordkey <= 0x7FFFFFFF)
    if (j > 0 && sord[j - 1] == o) return;           // not run start
    if (j + 1 >= M2 || sord[j + 1] != o) return;     // run length 1
    int e = j + 1;
    while (e < M2 && sord[e] == o) e++;
    for (int a = j + 1; a < e; a++) {                // tiny runs: insertion sort
        uint32_t kx = skey[a];
        int t = a;
        while (t > j && skey[t - 1] > kx) { skey[t] = skey[t - 1]; t--; }
        skey[t] = kx;
    }
}

__global__ void output_kernel(const uint32_t* __restrict__ sord,
                              const uint32_t* __restrict__ skey,
                              int R, int write_idx, int write_val, int val_off,
                              float* __restrict__ out) {
    int r = blockIdx.x * blockDim.x + threadIdx.x;
    if (r >= R) return;
    uint32_t key = skey[r];
    if (write_idx) {
        out[2 * r]     = (float)(key >> 12);
        out[2 * r + 1] = (float)(key & 4095u);
    }
    if (write_val) {
        uint32_t u = ~sord[r];
        uint32_t b = (u & 0x80000000u) ? (u ^ 0x80000000u) : ~u;
        out[val_off + r] = __uint_as_float(b);
    }
}

extern "C" void kernel_launch(void* const* d_in, const int* in_sizes, int n_in,
                              void* d_out, int out_size) {
    (void)n_in;
    const int*   samp = (const int*)d_in[0];
    const int*   ridx = (const int*)d_in[1];
    const float* rval = (const float*)d_in[2];
    const float* grad = (const float*)d_in[3];

    int S = in_sizes[0];
    int R = in_sizes[2];
    int K = S + R;
    if (K > MAX_K) K = MAX_K;

    double frac = (double)S / NUMEL_D;
    float adj = (float)(1.0 - frac * (1.0 - 0.95));

    uint32_t *cnt, *vslot, *dk, *dk2, *dp, *dp2, *di, *dv;
    uint32_t *cord, *ckey, *sord, *skey, *hist, *super, *Bp, *dcur, *ccur;
    unsigned long long* heads;
    void* tmp;
    cudaGetSymbolAddress((void**)&cnt,  g_cnt);
    cudaGetSymbolAddress((void**)&vslot,g_vslot);
    cudaGetSymbolAddress((void**)&heads,g_heads);
    cudaGetSymbolAddress((void**)&dk,   g_dk);
    cudaGetSymbolAddress((void**)&dk2,  g_dk2);
    cudaGetSymbolAddress((void**)&dp,   g_dp);
    cudaGetSymbolAddress((void**)&dp2,  g_dp2);
    cudaGetSymbolAddress((void**)&di,   g_di);
    cudaGetSymbolAddress((void**)&dv,   g_dv);
    cudaGetSymbolAddress((void**)&cord, g_cord);
    cudaGetSymbolAddress((void**)&ckey, g_ckey);
    cudaGetSymbolAddress((void**)&sord, g_sord);
    cudaGetSymbolAddress((void**)&skey, g_skey);
    cudaGetSymbolAddress((void**)&hist, g_hist);
    cudaGetSymbolAddress((void**)&super,g_super);
    cudaGetSymbolAddress((void**)&Bp,   g_B);
    cudaGetSymbolAddress((void**)&dcur, g_dcur);
    cudaGetSymbolAddress((void**)&ccur, g_ccur);
    cudaGetSymbolAddress(&tmp, g_temp);
    const size_t TMPB = (size_t)32u << 20;

    const int BLK = 256;
    const int GK = (K + BLK - 1) / BLK;

    // per-replay re-init
    cudaMemsetAsync(cnt,   0,    (size_t)(NUMEL / 4) * sizeof(uint32_t));
    cudaMemsetAsync(vslot, 0xFF, (size_t)NUMEL * sizeof(uint32_t));
    cudaMemsetAsync(hist,  0,    HIST_BINS * sizeof(uint32_t));
    cudaMemsetAsync(dcur,  0,    sizeof(uint32_t));
    cudaMemsetAsync(ccur,  0,    sizeof(uint32_t));
    cudaMemsetAsync(dk,    0xFF, (size_t)DUPN * sizeof(uint32_t));  // pad sorts last
    cudaMemsetAsync(cord,  0xFF, (size_t)M2 * sizeof(uint32_t));    // pad sorts last

    // 1) exact multiplicity per key (packed u8 counts, L2-resident)
    count_kernel<<<GK, BLK>>>(samp, ridx, S, K, cnt);

    // 2) classify: singles & pairs resolved inline, >=3 appended to dup list
    classify_kernel<<<GK, BLK>>>(samp, ridx, grad, rval, S, K, adj,
                                 cnt, vslot, heads, dcur, dk, dp, di, dv, hist);

    // 3) sort dup entries by key (stable), restore order, emit group heads
    {
        size_t need = 0;
        cub::DeviceRadixSort::SortPairs(nullptr, need, dk, dk2, dp, dp2, DUPN, 0, 32);
        if (need <= TMPB)
            cub::DeviceRadixSort::SortPairs(tmp, need, dk, dk2, dp, dp2, DUPN, 0, 32);
    }
    dupsum_kernel<<<(DUPN + BLK - 1) / BLK, BLK>>>(dk2, dp2, di, dv, heads, hist);

    // 4) threshold B (bin-granular, keeps all ties of the R-th element)
    coarse_kernel<<<1024, 256>>>(hist, super);
    select_kernel<<<1, 1024>>>(super, hist, (uint32_t)R, Bp);

    // 5) atomic-append candidate filter (order irrelevant; tie-fix restores it)
    filter_kernel<<<GK, BLK>>>(heads, Bp, K, ccur, cord, ckey);

    // 6) sort candidates by ordkey
    {
        size_t need = 0;
        cub::DeviceRadixSort::SortPairs(nullptr, need, cord, sord, ckey, skey, M2, 0, 32);
        if (need <= TMPB)
            cub::DeviceRadixSort::SortPairs(tmp, need, cord, sord, ckey, skey, M2, 0, 32);
    }

    // 7) exact tie-break: ascending key within each equal-value run
    tiefix_kernel<<<(M2 + BLK - 1) / BLK, BLK>>>(sord, skey);

    // 8) emit [new_index (R,2), top_vals (R)] as f32
    int write_idx = 1, write_val = 1, val_off = 2 * R;
    if (out_size == R)          { write_idx = 0; val_off = 0; }
    else if (out_size == 2 * R) { write_val = 0; }
    output_kernel<<<(R + BLK - 1) / BLK, BLK>>>(sord, skey, R,
                                                write_idx, write_val, val_off,
                                                (float*)d_out);
}

// round 8
// speedup vs baseline: 1.1681x; 1.0852x over previous
#include <cuda_runtime.h>
#include <cstdint>
#include <cub/cub.cuh>

// Problem constants
#define C_DIM     4096
#define NUMEL_D   16777216.0
#define MAX_K     4500000               // >= S + R = 4,404,019
#define M2        1114112               // candidate sort size: R + 64K slack
#define HIST_BINS (1u << 18)            // ordkey >> 13
#define TEMP_BYTES (48u * 1024u * 1024u)

// Static device scratch (allocation-free per harness rules)
__device__ uint32_t g_ka[MAX_K];        // pack keys (sort1 in)
__device__ uint32_t g_kb[MAX_K];        // sort1 key out (key-sorted keys)
__device__ uint32_t g_va[MAX_K];        // pack value bits (sort1 payload in)
__device__ uint32_t g_vb[MAX_K];        // sort1 payload out (key-ordered value bits)
__device__ uint32_t g_w [MAX_K];        // per-slot head ordkey (0xFFFFFFFF = non-head)
__device__ uint32_t g_cord[M2], g_ckey[M2];  // candidates (append)
__device__ uint32_t g_sord[M2], g_skey[M2];  // sorted candidates
__device__ uint32_t g_hist[HIST_BINS];
__device__ uint32_t g_super[1024];
__device__ uint32_t g_B[1];
__device__ uint32_t g_ccur[1];
__device__ unsigned char g_temp[TEMP_BYTES];

static __device__ __forceinline__ uint32_t f32_to_ord(uint32_t b) {
    return b ^ ((uint32_t)((int32_t)b >> 31) | 0x80000000u);
}

__global__ void pack_kernel(const int* __restrict__ samp,
                            const int* __restrict__ ridx,
                            const float* __restrict__ grad,
                            const float* __restrict__ rval,
                            int S, int K, float adj,
                            uint32_t* __restrict__ keys,
                            uint32_t* __restrict__ vals) {
    int i = blockIdx.x * blockDim.x + threadIdx.x;
    if (i >= K) return;
    uint32_t key; float v;
    if (i < S) {
        key = (uint32_t)samp[i];
        v = fabsf(grad[i]);
    } else {
        int r = i - S;
        key = (uint32_t)ridx[2 * r] * (uint32_t)C_DIM + (uint32_t)ridx[2 * r + 1];
        v = adj * rval[r];
    }
    keys[i] = key;
    vals[i] = __float_as_uint(v);
}

// Per segment-head: sum values sequentially (stable sort1 => original order),
// emit ~ord(sum); non-heads 0xFFFFFFFF. Histogram heads for threshold pick.
__global__ void headsum_kernel(const uint32_t* __restrict__ skeys,
                               const uint32_t* __restrict__ svals,
                               int K,
                               uint32_t* __restrict__ w,
                               uint32_t* __restrict__ hist) {
    int j = blockIdx.x * blockDim.x + threadIdx.x;
    if (j >= K) return;
    uint32_t key = skeys[j];
    bool head = (j == 0) || (skeys[j - 1] != key);
    if (!head) {
        w[j] = 0xFFFFFFFFu;
        return;
    }
    float sum = 0.0f;
    int t = j;
    while (t < K && skeys[t] == key) {
        sum += __uint_as_float(svals[t]);   // sequential, matches XLA scatter-add order
        ++t;
    }
    uint32_t ordk = ~f32_to_ord(__float_as_uint(sum));  // <= 0x7FFFFFFF (sum >= 0)
    w[j] = ordk;
    atomicAdd(&hist[ordk >> 13], 1u);
}

__global__ void coarse_kernel(const uint32_t* __restrict__ hist,
                              uint32_t* __restrict__ super) {
    typedef cub::BlockReduce<uint32_t, 256> BR;
    __shared__ typename BR::TempStorage ts;
    uint32_t v = hist[blockIdx.x * 256 + threadIdx.x];
    uint32_t s = BR(ts).Sum(v);
    if (threadIdx.x == 0) super[blockIdx.x] = s;
}

// Single block: smallest bin boundary B with #heads{ordkey < B} >= R.
__global__ void select_kernel(const uint32_t* __restrict__ super,
                              const uint32_t* __restrict__ hist,
                              uint32_t R, uint32_t* __restrict__ Bout) {
    typedef cub::BlockScan<uint32_t, 1024> BS;
    __shared__ typename BS::TempStorage ts;
    __shared__ uint32_t s_sb, s_base2;
    if (threadIdx.x == 0) { s_sb = 0xFFFFFFFFu; s_base2 = 0; }
    __syncthreads();
    uint32_t v = super[threadIdx.x];
    uint32_t inc;
    BS(ts).InclusiveSum(v, inc);
    if (inc >= R && (inc - v) < R) { s_sb = threadIdx.x; s_base2 = inc - v; }
    __syncthreads();
    if (s_sb == 0xFFFFFFFFu) {                // pathological: fewer heads than R
        if (threadIdx.x == 0) Bout[0] = 0xFFFFFFFFu;
        return;
    }
    uint32_t sb = s_sb, base = s_base2;
    __syncthreads();                          // before TempStorage reuse
    uint32_t h = (threadIdx.x < 256) ? hist[sb * 256 + threadIdx.x] : 0u;
    uint32_t inc1;
    BS(ts).InclusiveSum(h, inc1);
    if (threadIdx.x < 256) {
        uint32_t excl = inc1 - h;
        if (base + inc1 >= R && base + excl < R)
            Bout[0] = ((sb * 256u + threadIdx.x) + 1u) << 13;
    }
}

// Atomic-append candidate filter. Append order is nondeterministic; tiefix
// after the (deterministic-on-values) sort restores the exact key order.
__global__ void filter_kernel(const uint32_t* __restrict__ w,
                              const uint32_t* __restrict__ skeys,
                              const uint32_t* __restrict__ Bp, int K,
                              uint32_t* __restrict__ ccur,
                              uint32_t* __restrict__ cord,
                              uint32_t* __restrict__ ckey) {
    int j = blockIdx.x * blockDim.x + threadIdx.x;
    if (j >= K) return;
    uint32_t x = w[j];
    if (x < *Bp) {
        uint32_t p = atomicAdd(ccur, 1u);    // ptxas warp-aggregates (REDUX)
        if (p < (uint32_t)M2) {
            cord[p] = x;
            ckey[p] = skeys[j];
        }
    }
}

// Ascending key within each equal-ordkey run => exact lax.top_k tie-break.
__global__ void tiefix_kernel(const uint32_t* __restrict__ sord,
                              uint32_t* __restrict__ skey) {
    int j = blockIdx.x * blockDim.x + threadIdx.x;
    if (j >= M2) return;
    uint32_t o = sord[j];
    if (o == 0xFFFFFFFFu) return;                    // pad (real ordkey <= 0x7FFFFFFF)
    if (j > 0 && sord[j - 1] == o) return;           // not run start
    if (j + 1 >= M2 || sord[j + 1] != o) return;     // run length 1
    int e = j + 1;
    while (e < M2 && sord[e] == o) e++;
    for (int a = j + 1; a < e; a++) {                // tiny runs: insertion sort
        uint32_t kx = skey[a];
        int t = a;
        while (t > j && skey[t - 1] > kx) { skey[t] = skey[t - 1]; t--; }
        skey[t] = kx;
    }
}

__global__ void output_kernel(const uint32_t* __restrict__ sord,
                              const uint32_t* __restrict__ skey,
                              int R, int write_idx, int write_val, int val_off,
                              float* __restrict__ out) {
    int r = blockIdx.x * blockDim.x + threadIdx.x;
    if (r >= R) return;
    uint32_t key = skey[r];
    if (write_idx) {
        out[2 * r]     = (float)(key >> 12);
        out[2 * r + 1] = (float)(key & 4095u);
    }
    if (write_val) {
        uint32_t u = ~sord[r];
        uint32_t b = (u & 0x80000000u) ? (u ^ 0x80000000u) : ~u;
        out[val_off + r] = __uint_as_float(b);
    }
}

extern "C" void kernel_launch(void* const* d_in, const int* in_sizes, int n_in,
                              void* d_out, int out_size) {
    (void)n_in;
    const int*   samp = (const int*)d_in[0];
    const int*   ridx = (const int*)d_in[1];
    const float* rval = (const float*)d_in[2];
    const float* grad = (const float*)d_in[3];

    int S = in_sizes[0];
    int R = in_sizes[2];
    int K = S + R;
    if (K > MAX_K) K = MAX_K;

    double frac = (double)S / NUMEL_D;
    float adj = (float)(1.0 - frac * (1.0 - 0.95));

    uint32_t *ka, *kb, *va, *vb, *w;
    uint32_t *cord, *ckey, *sord, *skey, *hist, *super, *Bp, *ccur;
    void* tmp;
    cudaGetSymbolAddress((void**)&ka, g_ka);
    cudaGetSymbolAddress((void**)&kb, g_kb);
    cudaGetSymbolAddress((void**)&va, g_va);
    cudaGetSymbolAddress((void**)&vb, g_vb);
    cudaGetSymbolAddress((void**)&w,  g_w);
    cudaGetSymbolAddress((void**)&cord, g_cord);
    cudaGetSymbolAddress((void**)&ckey, g_ckey);
    cudaGetSymbolAddress((void**)&sord, g_sord);
    cudaGetSymbolAddress((void**)&skey, g_skey);
    cudaGetSymbolAddress((void**)&hist, g_hist);
    cudaGetSymbolAddress((void**)&super, g_super);
    cudaGetSymbolAddress((void**)&Bp, g_B);
    cudaGetSymbolAddress((void**)&ccur, g_ccur);
    cudaGetSymbolAddress(&tmp, g_temp);
    const size_t TMPB = (size_t)TEMP_BYTES;

    const int BLK = 256;
    const int GK = (K + BLK - 1) / BLK;

    // per-replay re-init (small)
    cudaMemsetAsync(hist, 0, HIST_BINS * sizeof(uint32_t));
    cudaMemsetAsync(ccur, 0, sizeof(uint32_t));
    cudaMemsetAsync(cord, 0xFF, (size_t)M2 * sizeof(uint32_t));  // pads sort last

    // 1) Build (key, value-bits)
    pack_kernel<<<GK, BLK>>>(samp, ridx, grad, rval, S, K, adj, ka, va);

    // 2) Stable sort by 24-bit key, payload = value bits (original order per key kept)
    {
        size_t need = 0;
        cub::DeviceRadixSort::SortPairs(nullptr, need, ka, kb, va, vb, K, 0, 24);
        if (need <= TMPB)
            cub::DeviceRadixSort::SortPairs(tmp, need, ka, kb, va, vb, K, 0, 24);
    }

    // 3) Ordered per-segment sums -> head ordkeys + histogram
    headsum_kernel<<<GK, BLK>>>(kb, vb, K, w, hist);

    // 4) Threshold B (bin-granular, keeps all ties of the R-th element)
    coarse_kernel<<<1024, 256>>>(hist, super);
    select_kernel<<<1, 1024>>>(super, hist, (uint32_t)R, Bp);

    // 5) Atomic-append candidate filter
    filter_kernel<<<GK, BLK>>>(w, kb, Bp, K, ccur, cord, ckey);

    // 6) Sort candidates by ordkey (deterministic on values)
    {
        size_t need = 0;
        cub::DeviceRadixSort::SortPairs(nullptr, need, cord, sord, ckey, skey, M2, 0, 32);
        if (need <= TMPB)
            cub::DeviceRadixSort::SortPairs(tmp, need, cord, sord, ckey, skey, M2, 0, 32);
    }

    // 7) Exact tie-break: ascending key within each equal-value run
    tiefix_kernel<<<(M2 + BLK - 1) / BLK, BLK>>>(sord, skey);

    // 8) Emit [new_index (R,2), top_vals (R)] as f32
    int write_idx = 1, write_val = 1, val_off = 2 * R;
    if (out_size == R)          { write_idx = 0; val_off = 0; }
    else if (out_size == 2 * R) { write_val = 0; }
    output_kernel<<<(R + BLK - 1) / BLK, BLK>>>(sord, skey, R,
                                                write_idx, write_val, val_off,
                                                (float*)d_out);
}

// round 9
// speedup vs baseline: 1.3652x; 1.1687x over previous
#include <cuda_runtime.h>
#include <cstdint>
#include <cub/cub.cuh>

// Problem constants
#define C_DIM     4096
#define NUMEL_D   16777216.0
#define MAX_K     4500000               // >= S + R = 4,404,019
#define M2        1114112               // candidate sort size: R + 64K slack
#define HIST_BINS (1u << 18)            // ordkey >> 13
#define TEMP_BYTES (48u * 1024u * 1024u)

// Static device scratch (allocation-free per harness rules)
__device__ uint32_t g_ka[MAX_K];        // pack keys (sort1 in)
__device__ uint32_t g_kb[MAX_K];        // sort1 key out (key-sorted keys)
__device__ uint32_t g_va[MAX_K];        // pack value bits (sort1 payload in)
__device__ uint32_t g_vb[MAX_K];        // sort1 payload out (key-ordered value bits)
__device__ uint32_t g_w [MAX_K];        // per-slot head ordkey (0xFFFFFFFF = non-head)
__device__ uint32_t g_cord[M2], g_ckey[M2];  // candidates (append)
__device__ uint32_t g_sord[M2], g_skey[M2];  // sorted candidates
__device__ uint32_t g_hist[HIST_BINS];
__device__ uint32_t g_super[1024];
__device__ uint32_t g_B[1];
__device__ uint32_t g_ccur[1];
__device__ unsigned char g_temp[TEMP_BYTES];

static __device__ __forceinline__ uint32_t f32_to_ord(uint32_t b) {
    return b ^ ((uint32_t)((int32_t)b >> 31) | 0x80000000u);
}

__global__ void pack_kernel(const int* __restrict__ samp,
                            const int* __restrict__ ridx,
                            const float* __restrict__ grad,
                            const float* __restrict__ rval,
                            int S, int K, float adj,
                            uint32_t* __restrict__ keys,
                            uint32_t* __restrict__ vals) {
    int i = blockIdx.x * blockDim.x + threadIdx.x;
    if (i >= K) return;
    uint32_t key; float v;
    if (i < S) {
        key = (uint32_t)samp[i];
        v = fabsf(grad[i]);
    } else {
        int r = i - S;
        key = (uint32_t)ridx[2 * r] * (uint32_t)C_DIM + (uint32_t)ridx[2 * r + 1];
        v = adj * rval[r];
    }
    keys[i] = key;
    vals[i] = __float_as_uint(v);
}

// Per segment-head: sum values sequentially (stable sort1 => original order),
// emit ~ord(sum); non-heads 0xFFFFFFFF. Histogram heads for threshold pick.
__global__ void headsum_kernel(const uint32_t* __restrict__ skeys,
                               const uint32_t* __restrict__ svals,
                               int K,
                               uint32_t* __restrict__ w,
                               uint32_t* __restrict__ hist) {
    int j = blockIdx.x * blockDim.x + threadIdx.x;
    if (j >= K) return;
    uint32_t key = skeys[j];
    bool head = (j == 0) || (skeys[j - 1] != key);
    if (!head) {
        w[j] = 0xFFFFFFFFu;
        return;
    }
    float sum = 0.0f;
    int t = j;
    while (t < K && skeys[t] == key) {
        sum += __uint_as_float(svals[t]);   // sequential, matches XLA scatter-add order
        ++t;
    }
    uint32_t ordk = ~f32_to_ord(__float_as_uint(sum));  // <= 0x7FFFFFFF (sum >= 0)
    w[j] = ordk;
    atomicAdd(&hist[ordk >> 13], 1u);
}

__global__ void coarse_kernel(const uint32_t* __restrict__ hist,
                              uint32_t* __restrict__ super) {
    typedef cub::BlockReduce<uint32_t, 256> BR;
    __shared__ typename BR::TempStorage ts;
    uint32_t v = hist[blockIdx.x * 256 + threadIdx.x];
    uint32_t s = BR(ts).Sum(v);
    if (threadIdx.x == 0) super[blockIdx.x] = s;
}

// Single block: smallest bin boundary B with #heads{ordkey < B} >= R.
__global__ void select_kernel(const uint32_t* __restrict__ super,
                              const uint32_t* __restrict__ hist,
                              uint32_t R, uint32_t* __restrict__ Bout) {
    typedef cub::BlockScan<uint32_t, 1024> BS;
    __shared__ typename BS::TempStorage ts;
    __shared__ uint32_t s_sb, s_base2;
    if (threadIdx.x == 0) { s_sb = 0xFFFFFFFFu; s_base2 = 0; }
    __syncthreads();
    uint32_t v = super[threadIdx.x];
    uint32_t inc;
    BS(ts).InclusiveSum(v, inc);
    if (inc >= R && (inc - v) < R) { s_sb = threadIdx.x; s_base2 = inc - v; }
    __syncthreads();
    if (s_sb == 0xFFFFFFFFu) {                // pathological: fewer heads than R
        if (threadIdx.x == 0) Bout[0] = 0xFFFFFFFFu;
        return;
    }
    uint32_t sb = s_sb, base = s_base2;
    __syncthreads();                          // before TempStorage reuse
    uint32_t h = (threadIdx.x < 256) ? hist[sb * 256 + threadIdx.x] : 0u;
    uint32_t inc1;
    BS(ts).InclusiveSum(h, inc1);
    if (threadIdx.x < 256) {
        uint32_t excl = inc1 - h;
        if (base + inc1 >= R && base + excl < R)
            Bout[0] = ((sb * 256u + threadIdx.x) + 1u) << 13;
    }
}

// Block-aggregated candidate append: ONE global atomic per block (8.6K total),
// intra-block ranks via BlockScan. Cross-block order nondeterministic; tiefix
// after the (value-deterministic) sort restores the exact key order.
__global__ void __launch_bounds__(512) filter_kernel(
        const uint32_t* __restrict__ w,
        const uint32_t* __restrict__ skeys,
        const uint32_t* __restrict__ Bp, int K,
        uint32_t* __restrict__ ccur,
        uint32_t* __restrict__ cord,
        uint32_t* __restrict__ ckey) {
    int j = blockIdx.x * 512 + threadIdx.x;
    uint32_t B = *Bp;
    uint32_t x = (j < K) ? w[j] : 0xFFFFFFFFu;
    uint32_t pred = (x < B) ? 1u : 0u;
    typedef cub::BlockScan<uint32_t, 512> BS;
    __shared__ typename BS::TempStorage ts;
    __shared__ uint32_t s_base;
    uint32_t rank, total;
    BS(ts).ExclusiveSum(pred, rank, total);
    if (threadIdx.x == 0)
        s_base = (total > 0) ? atomicAdd(ccur, total) : 0u;
    __syncthreads();
    if (pred) {
        uint32_t p = s_base + rank;
        if (p < (uint32_t)M2) {
            cord[p] = x;
            ckey[p] = skeys[j];
        }
    }
}

// Ascending key within each equal-ordkey run => exact lax.top_k tie-break.
__global__ void tiefix_kernel(const uint32_t* __restrict__ sord,
                              uint32_t* __restrict__ skey) {
    int j = blockIdx.x * blockDim.x + threadIdx.x;
    if (j >= M2) return;
    uint32_t o = sord[j];
    if (o == 0xFFFFFFFFu) return;                    // pad (real ordkey <= 0x7FFFFFFF)
    if (j > 0 && sord[j - 1] == o) return;           // not run start
    if (j + 1 >= M2 || sord[j + 1] != o) return;     // run length 1
    int e = j + 1;
    while (e < M2 && sord[e] == o) e++;
    for (int a = j + 1; a < e; a++) {                // tiny runs: insertion sort
        uint32_t kx = skey[a];
        int t = a;
        while (t > j && skey[t - 1] > kx) { skey[t] = skey[t - 1]; t--; }
        skey[t] = kx;
    }
}

__global__ void output_kernel(const uint32_t* __restrict__ sord,
                              const uint32_t* __restrict__ skey,
                              int R, int write_idx, int write_val, int val_off,
                              float* __restrict__ out) {
    int r = blockIdx.x * blockDim.x + threadIdx.x;
    if (r >= R) return;
    uint32_t key = skey[r];
    if (write_idx) {
        out[2 * r]     = (float)(key >> 12);
        out[2 * r + 1] = (float)(key & 4095u);
    }
    if (write_val) {
        uint32_t u = ~sord[r];
        uint32_t b = (u & 0x80000000u) ? (u ^ 0x80000000u) : ~u;
        out[val_off + r] = __uint_as_float(b);
    }
}

extern "C" void kernel_launch(void* const* d_in, const int* in_sizes, int n_in,
                              void* d_out, int out_size) {
    (void)n_in;
    const int*   samp = (const int*)d_in[0];
    const int*   ridx = (const int*)d_in[1];
    const float* rval = (const float*)d_in[2];
    const float* grad = (const float*)d_in[3];

    int S = in_sizes[0];
    int R = in_sizes[2];
    int K = S + R;
    if (K > MAX_K) K = MAX_K;

    double frac = (double)S / NUMEL_D;
    float adj = (float)(1.0 - frac * (1.0 - 0.95));

    uint32_t *ka, *kb, *va, *vb, *w;
    uint32_t *cord, *ckey, *sord, *skey, *hist, *super, *Bp, *ccur;
    void* tmp;
    cudaGetSymbolAddress((void**)&ka, g_ka);
    cudaGetSymbolAddress((void**)&kb, g_kb);
    cudaGetSymbolAddress((void**)&va, g_va);
    cudaGetSymbolAddress((void**)&vb, g_vb);
    cudaGetSymbolAddress((void**)&w,  g_w);
    cudaGetSymbolAddress((void**)&cord, g_cord);
    cudaGetSymbolAddress((void**)&ckey, g_ckey);
    cudaGetSymbolAddress((void**)&sord, g_sord);
    cudaGetSymbolAddress((void**)&skey, g_skey);
    cudaGetSymbolAddress((void**)&hist, g_hist);
    cudaGetSymbolAddress((void**)&super, g_super);
    cudaGetSymbolAddress((void**)&Bp, g_B);
    cudaGetSymbolAddress((void**)&ccur, g_ccur);
    cudaGetSymbolAddress(&tmp, g_temp);
    const size_t TMPB = (size_t)TEMP_BYTES;

    const int BLK = 256;
    const int GK = (K + BLK - 1) / BLK;

    // per-replay re-init (small)
    cudaMemsetAsync(hist, 0, HIST_BINS * sizeof(uint32_t));
    cudaMemsetAsync(ccur, 0, sizeof(uint32_t));
    cudaMemsetAsync(cord, 0xFF, (size_t)M2 * sizeof(uint32_t));  // pads sort last

    // 1) Build (key, value-bits)
    pack_kernel<<<GK, BLK>>>(samp, ridx, grad, rval, S, K, adj, ka, va);

    // 2) Stable sort by 24-bit key, payload = value bits (original order per key kept)
    {
        size_t need = 0;
        cub::DeviceRadixSort::SortPairs(nullptr, need, ka, kb, va, vb, K, 0, 24);
        if (need <= TMPB)
            cub::DeviceRadixSort::SortPairs(tmp, need, ka, kb, va, vb, K, 0, 24);
    }

    // 3) Ordered per-segment sums -> head ordkeys + histogram
    headsum_kernel<<<GK, BLK>>>(kb, vb, K, w, hist);

    // 4) Threshold B (bin-granular, keeps all ties of the R-th element)
    coarse_kernel<<<1024, 256>>>(hist, super);
    select_kernel<<<1, 1024>>>(super, hist, (uint32_t)R, Bp);

    // 5) Block-aggregated candidate append
    filter_kernel<<<(K + 511) / 512, 512>>>(w, kb, Bp, K, ccur, cord, ckey);

    // 6) Sort candidates by ordkey (deterministic on values)
    {
        size_t need = 0;
        cub::DeviceRadixSort::SortPairs(nullptr, need, cord, sord, ckey, skey, M2, 0, 32);
        if (need <= TMPB)
            cub::DeviceRadixSort::SortPairs(tmp, need, cord, sord, ckey, skey, M2, 0, 32);
    }

    // 7) Exact tie-break: ascending key within each equal-value run
    tiefix_kernel<<<(M2 + BLK - 1) / BLK, BLK>>>(sord, skey);

    // 8) Emit [new_index (R,2), top_vals (R)] as f32
    int write_idx = 1, write_val = 1, val_off = 2 * R;
    if (out_size == R)          { write_idx = 0; val_off = 0; }
    else if (out_size == 2 * R) { write_val = 0; }
    output_kernel<<<(R + BLK - 1) / BLK, BLK>>>(sord, skey, R,
                                                write_idx, write_val, val_off,
                                                (float*)d_out);
}

// round 10
// speedup vs baseline: 1.4517x; 1.0634x over previous
#include <cuda_runtime.h>
#include <cstdint>
#include <cub/cub.cuh>

// Problem constants
#define C_DIM     4096
#define NUMEL     16777216
#define NUMEL_D   16777216.0
#define MAX_K     4500000               // >= S + R = 4,404,019
#define DUPN      1572864               // cap for entries on duplicated keys (~1.02M expected)
#define M2        1114112               // candidate sort size: R + 64K slack
#define HIST_BINS (1u << 18)            // ordkey >> 13
#define TEMP_BYTES (48u * 1024u * 1024u)

// Static device scratch (allocation-free per harness rules)
__device__ uint32_t g_cnt[NUMEL / 4];        // packed u8 multiplicity, 16MB (L2-resident)
__device__ uint32_t g_hord[MAX_K];           // dense head ordkeys
__device__ uint32_t g_hkey[MAX_K];           // dense head keys
__device__ uint32_t g_dk[DUPN], g_dk2[DUPN]; // dup keys in/out
__device__ uint32_t g_dp[DUPN], g_dp2[DUPN]; // dup slot payload in/out
__device__ uint32_t g_di[DUPN], g_dv[DUPN];  // dup origidx / value bits (by slot)
__device__ uint32_t g_cord[M2], g_ckey[M2];  // candidates
__device__ uint32_t g_sord[M2], g_skey[M2];  // sorted candidates
__device__ uint32_t g_hist[HIST_BINS];
__device__ uint32_t g_super[1024];
__device__ uint32_t g_B[1];
__device__ uint32_t g_hcur[1], g_dcur[1], g_ccur[1];
__device__ unsigned char g_temp[TEMP_BYTES];

static __device__ __forceinline__ uint32_t f32_to_ord(uint32_t b) {
    return b ^ ((uint32_t)((int32_t)b >> 31) | 0x80000000u);
}
static __device__ __forceinline__ uint32_t make_key(const int* __restrict__ samp,
                                                    const int* __restrict__ ridx,
                                                    int S, int i) {
    if (i < S) return (uint32_t)samp[i];
    int r = i - S;
    return (uint32_t)ridx[2 * r] * (uint32_t)C_DIM + (uint32_t)ridx[2 * r + 1];
}

__global__ void __launch_bounds__(512) count_kernel(
        const int* __restrict__ samp, const int* __restrict__ ridx,
        int S, int K, uint32_t* __restrict__ cnt) {
    int i = blockIdx.x * 512 + threadIdx.x;
    if (i >= K) return;
    uint32_t key = make_key(samp, ridx, S, i);
    atomicAdd(&cnt[key >> 2], 1u << ((key & 3u) * 8u));
}

// Singletons -> dense head list (ordkey,key). Duplicated-key entries -> dup list.
// Both appends block-aggregated (one global atomic per block per list).
__global__ void __launch_bounds__(512) classify_kernel(
        const int* __restrict__ samp, const int* __restrict__ ridx,
        const float* __restrict__ grad, const float* __restrict__ rval,
        int S, int K, float adj,
        const uint32_t* __restrict__ cnt,
        uint32_t* __restrict__ hcur, uint32_t* __restrict__ hord, uint32_t* __restrict__ hkey,
        uint32_t* __restrict__ dcur, uint32_t* __restrict__ dk, uint32_t* __restrict__ dp,
        uint32_t* __restrict__ di, uint32_t* __restrict__ dv,
        uint32_t* __restrict__ hist) {
    int i = blockIdx.x * 512 + threadIdx.x;
    bool valid = (i < K);
    uint32_t key = 0, bits = 0, c = 0;
    if (valid) {
        key = make_key(samp, ridx, S, i);
        float v = (i < S) ? fabsf(grad[i]) : adj * rval[i - S];
        bits = __float_as_uint(v);
        c = (cnt[key >> 2] >> ((key & 3u) * 8u)) & 0xFFu;
    }
    uint32_t isS = (valid && c == 1u) ? 1u : 0u;
    uint32_t isD = (valid && c >= 2u) ? 1u : 0u;

    typedef cub::BlockScan<uint32_t, 512> BS;
    __shared__ typename BS::TempStorage ts;
    __shared__ uint32_t s_baseS, s_baseD;

    uint32_t rankS, totS;
    BS(ts).ExclusiveSum(isS, rankS, totS);
    if (threadIdx.x == 0) s_baseS = (totS > 0) ? atomicAdd(hcur, totS) : 0u;
    __syncthreads();
    uint32_t rankD, totD;
    BS(ts).ExclusiveSum(isD, rankD, totD);
    if (threadIdx.x == 0) s_baseD = (totD > 0) ? atomicAdd(dcur, totD) : 0u;
    __syncthreads();

    if (isS) {
        uint32_t p = s_baseS + rankS;          // p < K <= MAX_K always
        uint32_t ordk = ~f32_to_ord(bits);     // singleton: sum == value, exact
        hord[p] = ordk;
        hkey[p] = key;
        atomicAdd(&hist[ordk >> 13], 1u);
    }
    if (isD) {
        uint32_t p = s_baseD + rankD;
        if (p < (uint32_t)DUPN) {
            dk[p] = key;
            dp[p] = p;
            di[p] = (uint32_t)i;
            dv[p] = bits;
        }
    }
}

// Dup list sorted by key (low 24 bits; pads keep 0xFFFFFFFF and segregate).
// Per group head: restore original order via min-origidx selection, sum
// sequentially (bit-exact vs XLA scatter-add), block-append head.
__global__ void __launch_bounds__(256) dupsum_kernel(
        const uint32_t* __restrict__ dk2, const uint32_t* __restrict__ dp2,
        const uint32_t* __restrict__ di,  const uint32_t* __restrict__ dv,
        uint32_t* __restrict__ hcur, uint32_t* __restrict__ hord,
        uint32_t* __restrict__ hkey, uint32_t* __restrict__ hist) {
    int j = blockIdx.x * 256 + threadIdx.x;
    uint32_t myord = 0, mykey = 0, have = 0;
    if (j < DUPN) {
        uint32_t k = dk2[j];
        uint32_t slot = dp2[j];
        if (slot < (uint32_t)DUPN) {                       // real entry (not pad)
            bool head = (j == 0) || (dk2[j - 1] != k);     // reals precede pads (stable sort)
            if (head) {
                int e = j + 1;
                while (e < DUPN && dk2[e] == k && dp2[e] < (uint32_t)DUPN) e++;
                int L = e - j;
                float sum = 0.0f;
                uint32_t lastEx = 0;
                for (int s = 0; s < L; s++) {              // tiny groups (<= ~10)
                    uint32_t best = 0xFFFFFFFFu, bv = 0;
                    for (int q = j; q < e; q++) {
                        uint32_t sl = dp2[q];
                        uint32_t oi = di[sl];
                        if (oi >= lastEx && oi < best) { best = oi; bv = dv[sl]; }
                    }
                    sum += __uint_as_float(bv);            // original order => exact
                    lastEx = best + 1u;
                }
                myord = ~f32_to_ord(__float_as_uint(sum));
                mykey = k & 0xFFFFFFu;
                have = 1;
            }
        }
    }
    typedef cub::BlockScan<uint32_t, 256> BS;
    __shared__ typename BS::TempStorage ts;
    __shared__ uint32_t s_base;
    uint32_t rank, total;
    BS(ts).ExclusiveSum(have, rank, total);
    if (threadIdx.x == 0) s_base = (total > 0) ? atomicAdd(hcur, total) : 0u;
    __syncthreads();
    if (have) {
        uint32_t p = s_base + rank;                        // total heads <= K <= MAX_K
        hord[p] = myord;
        hkey[p] = mykey;
        atomicAdd(&hist[myord >> 13], 1u);
    }
}

__global__ void coarse_kernel(const uint32_t* __restrict__ hist,
                              uint32_t* __restrict__ super) {
    typedef cub::BlockReduce<uint32_t, 256> BR;
    __shared__ typename BR::TempStorage ts;
    uint32_t v = hist[blockIdx.x * 256 + threadIdx.x];
    uint32_t s = BR(ts).Sum(v);
    if (threadIdx.x == 0) super[blockIdx.x] = s;
}

// Single block: smallest bin boundary B with #heads{ordkey < B} >= R.
__global__ void select_kernel(const uint32_t* __restrict__ super,
                              const uint32_t* __restrict__ hist,
                              uint32_t R, uint32_t* __restrict__ Bout) {
    typedef cub::BlockScan<uint32_t, 1024> BS;
    __shared__ typename BS::TempStorage ts;
    __shared__ uint32_t s_sb, s_base2;
    if (threadIdx.x == 0) { s_sb = 0xFFFFFFFFu; s_base2 = 0; }
    __syncthreads();
    uint32_t v = super[threadIdx.x];
    uint32_t inc;
    BS(ts).InclusiveSum(v, inc);
    if (inc >= R && (inc - v) < R) { s_sb = threadIdx.x; s_base2 = inc - v; }
    __syncthreads();
    if (s_sb == 0xFFFFFFFFu) {
        if (threadIdx.x == 0) Bout[0] = 0xFFFFFFFFu;
        return;
    }
    uint32_t sb = s_sb, base = s_base2;
    __syncthreads();
    uint32_t h = (threadIdx.x < 256) ? hist[sb * 256 + threadIdx.x] : 0u;
    uint32_t inc1;
    BS(ts).InclusiveSum(h, inc1);
    if (threadIdx.x < 256) {
        uint32_t excl = inc1 - h;
        if (base + inc1 >= R && base + excl < R)
            Bout[0] = ((sb * 256u + threadIdx.x) + 1u) << 13;
    }
}

// Block-aggregated candidate append over the dense head list.
__global__ void __launch_bounds__(512) filter_kernel(
        const uint32_t* __restrict__ hord, const uint32_t* __restrict__ hkey,
        const uint32_t* __restrict__ hcurp, const uint32_t* __restrict__ Bp,
        uint32_t* __restrict__ ccur,
        uint32_t* __restrict__ cord, uint32_t* __restrict__ ckey) {
    int j = blockIdx.x * 512 + threadIdx.x;
    uint32_t H = *hcurp;
    uint32_t B = *Bp;
    uint32_t x = (j < (int)H) ? hord[j] : 0xFFFFFFFFu;
    uint32_t pred = (x < B) ? 1u : 0u;
    typedef cub::BlockScan<uint32_t, 512> BS;
    __shared__ typename BS::TempStorage ts;
    __shared__ uint32_t s_base;
    uint32_t rank, total;
    BS(ts).ExclusiveSum(pred, rank, total);
    if (threadIdx.x == 0) s_base = (total > 0) ? atomicAdd(ccur, total) : 0u;
    __syncthreads();
    if (pred) {
        uint32_t p = s_base + rank;
        if (p < (uint32_t)M2) {
            cord[p] = x;
            ckey[p] = hkey[j];
        }
    }
}

// Ascending key within each equal-ordkey run => exact lax.top_k tie-break.
__global__ void tiefix_kernel(const uint32_t* __restrict__ sord,
                              uint32_t* __restrict__ skey) {
    int j = blockIdx.x * blockDim.x + threadIdx.x;
    if (j >= M2) return;
    uint32_t o = sord[j];
    if (o == 0xFFFFFFFFu) return;                    // pad
    if (j > 0 && sord[j - 1] == o) return;           // not run start
    if (j + 1 >= M2 || sord[j + 1] != o) return;     // run length 1
    int e = j + 1;
    while (e < M2 && sord[e] == o) e++;
    for (int a = j + 1; a < e; a++) {
        uint32_t kx = skey[a];
        int t = a;
        while (t > j && skey[t - 1] > kx) { skey[t] = skey[t - 1]; t--; }
        skey[t] = kx;
    }
}

__global__ void output_kernel(const uint32_t* __restrict__ sord,
                              const uint32_t* __restrict__ skey,
                              int R, int write_idx, int write_val, int val_off,
                              float* __restrict__ out) {
    int r = blockIdx.x * blockDim.x + threadIdx.x;
    if (r >= R) return;
    uint32_t key = skey[r];
    if (write_idx) {
        out[2 * r]     = (float)(key >> 12);
        out[2 * r + 1] = (float)(key & 4095u);
    }
    if (write_val) {
        uint32_t u = ~sord[r];
        uint32_t b = (u & 0x80000000u) ? (u ^ 0x80000000u) : ~u;
        out[val_off + r] = __uint_as_float(b);
    }
}

extern "C" void kernel_launch(void* const* d_in, const int* in_sizes, int n_in,
                              void* d_out, int out_size) {
    (void)n_in;
    const int*   samp = (const int*)d_in[0];
    const int*   ridx = (const int*)d_in[1];
    const float* rval = (const float*)d_in[2];
    const float* grad = (const float*)d_in[3];

    int S = in_sizes[0];
    int R = in_sizes[2];
    int K = S + R;
    if (K > MAX_K) K = MAX_K;

    double frac = (double)S / NUMEL_D;
    float adj = (float)(1.0 - frac * (1.0 - 0.95));

    uint32_t *cnt, *hord, *hkey, *dk, *dk2, *dp, *dp2, *di, *dv;
    uint32_t *cord, *ckey, *sord, *skey, *hist, *super, *Bp, *hcur, *dcur, *ccur;
    void* tmp;
    cudaGetSymbolAddress((void**)&cnt,  g_cnt);
    cudaGetSymbolAddress((void**)&hord, g_hord);
    cudaGetSymbolAddress((void**)&hkey, g_hkey);
    cudaGetSymbolAddress((void**)&dk,   g_dk);
    cudaGetSymbolAddress((void**)&dk2,  g_dk2);
    cudaGetSymbolAddress((void**)&dp,   g_dp);
    cudaGetSymbolAddress((void**)&dp2,  g_dp2);
    cudaGetSymbolAddress((void**)&di,   g_di);
    cudaGetSymbolAddress((void**)&dv,   g_dv);
    cudaGetSymbolAddress((void**)&cord, g_cord);
    cudaGetSymbolAddress((void**)&ckey, g_ckey);
    cudaGetSymbolAddress((void**)&sord, g_sord);
    cudaGetSymbolAddress((void**)&skey, g_skey);
    cudaGetSymbolAddress((void**)&hist, g_hist);
    cudaGetSymbolAddress((void**)&super,g_super);
    cudaGetSymbolAddress((void**)&Bp,   g_B);
    cudaGetSymbolAddress((void**)&hcur, g_hcur);
    cudaGetSymbolAddress((void**)&dcur, g_dcur);
    cudaGetSymbolAddress((void**)&ccur, g_ccur);
    cudaGetSymbolAddress(&tmp, g_temp);
    const size_t TMPB = (size_t)TEMP_BYTES;

    const int BLK = 256;
    const int GK512 = (K + 511) / 512;

    // per-replay re-init
    cudaMemsetAsync(cnt,  0,    (size_t)(NUMEL / 4) * sizeof(uint32_t)); // 16MB
    cudaMemsetAsync(hist, 0,    HIST_BINS * sizeof(uint32_t));           // 1MB
    cudaMemsetAsync(hcur, 0,    sizeof(uint32_t));
    cudaMemsetAsync(dcur, 0,    sizeof(uint32_t));
    cudaMemsetAsync(ccur, 0,    sizeof(uint32_t));
    cudaMemsetAsync(dk,   0xFF, (size_t)DUPN * sizeof(uint32_t));        // pads sort last
    cudaMemsetAsync(dp,   0xFF, (size_t)DUPN * sizeof(uint32_t));        // pad slots >= DUPN
    cudaMemsetAsync(cord, 0xFF, (size_t)M2 * sizeof(uint32_t));          // pads sort last

    // 1) multiplicity per key (L2-resident packed u8 table)
    count_kernel<<<GK512, 512>>>(samp, ridx, S, K, cnt);

    // 2) classify: singletons -> dense heads, duplicated-key entries -> dup list
    classify_kernel<<<GK512, 512>>>(samp, ridx, grad, rval, S, K, adj, cnt,
                                    hcur, hord, hkey, dcur, dk, dp, di, dv, hist);

    // 3) sort dup entries by key (stable; pads segregate), restore order, emit heads
    {
        size_t need = 0;
        cub::DeviceRadixSort::SortPairs(nullptr, need, dk, dk2, dp, dp2, DUPN, 0, 24);
        if (need <= TMPB)
            cub::DeviceRadixSort::SortPairs(tmp, need, dk, dk2, dp, dp2, DUPN, 0, 24);
    }
    dupsum_kernel<<<(DUPN + BLK - 1) / BLK, BLK>>>(dk2, dp2, di, dv,
                                                   hcur, hord, hkey, hist);

    // 4) threshold B (bin-granular, keeps all ties of the R-th element)
    coarse_kernel<<<1024, 256>>>(hist, super);
    select_kernel<<<1, 1024>>>(super, hist, (uint32_t)R, Bp);

    // 5) candidate filter over dense heads (block-aggregated append)
    filter_kernel<<<(MAX_K + 511) / 512, 512>>>(hord, hkey, hcur, Bp,
                                                ccur, cord, ckey);

    // 6) sort candidates by ordkey
    {
        size_t need = 0;
        cub::DeviceRadixSort::SortPairs(nullptr, need, cord, sord, ckey, skey, M2, 0, 32);
        if (need <= TMPB)
            cub::DeviceRadixSort::SortPairs(tmp, need, cord, sord, ckey, skey, M2, 0, 32);
    }

    // 7) exact tie-break: ascending key within each equal-value run
    tiefix_kernel<<<(M2 + BLK - 1) / BLK, BLK>>>(sord, skey);

    // 8) emit [new_index (R,2), top_vals (R)] as f32
    int write_idx = 1, write_val = 1, val_off = 2 * R;
    if (out_size == R)          { write_idx = 0; val_off = 0; }
    else if (out_size == 2 * R) { write_val = 0; }
    output_kernel<<<(R + BLK - 1) / BLK, BLK>>>(sord, skey, R,
                                                write_idx, write_val, val_off,
                                                (float*)d_out);
}